// round 2
// baseline (speedup 1.0000x reference)
#include <cuda_runtime.h>

#define TT 256
#define BB 8
#define EE 512
#define HH 1024
#define OO 32000
#define MM (TT*BB)       // 2048
#define GRID_RNN 128

__device__ float g_xproj[MM*HH];   // [t*8+b][h]
__device__ float g_hs[MM*HH];      // [t*8+b][h]  (hidden states per step)
__device__ unsigned g_ctr[TT];     // per-step grid-barrier counters

// ---------------------------------------------------------------------------
// Kernel 1: xproj[t][b][h] = sum_e embed[tok[b][t]][e] * W_ih[h][e] + b_ih[h]
// GEMM M=2048, N=1024, K=512 with gathered A. 64x64 tiles, 256 thr, 4x4 micro.
// Also zeroes the grid-barrier counters for the recurrence kernel.
// ---------------------------------------------------------------------------
__global__ __launch_bounds__(256, 2) void xproj_kernel(
    const void* __restrict__ tokens_raw, const float* __restrict__ embed,
    const float* __restrict__ W_ih, const float* __restrict__ b_ih)
{
    if (blockIdx.x == 0 && blockIdx.y == 0 && threadIdx.x < TT)
        g_ctr[threadIdx.x] = 0;

    __shared__ float As[16][68];   // [k][m], stride 68 (272B = 16*17, 16B aligned)
    __shared__ float Bs[16][68];   // [k][n]
    __shared__ int   stok[64];
    __shared__ int   mode64;

    int tid = threadIdx.x;
    int n0 = blockIdx.x * 64, m0 = blockIdx.y * 64;

    // Detect token dtype: int64 (odd 4B words all zero) vs int32.
    if (tid == 0) {
        const int* w = (const int*)tokens_raw;
        int z = 1;
        #pragma unroll 1
        for (int i = 1; i < 64; i += 2) if (w[i] != 0) z = 0;
        mode64 = z;
    }
    __syncthreads();
    if (tid < 64) {
        int r = m0 + tid; int tt = r >> 3, bb = r & 7;
        int idx = bb * TT + tt;
        stok[tid] = mode64 ? (int)((const long long*)tokens_raw)[idx]
                           : ((const int*)tokens_raw)[idx];
    }
    __syncthreads();

    int tx = tid & 15, ty = tid >> 4;
    float acc[4][4] = {};

    for (int kk = 0; kk < EE; kk += 16) {
        #pragma unroll
        for (int i = 0; i < 4; i++) {
            int lin = i * 256 + tid;
            int m = lin >> 4, k = lin & 15;
            As[k][m] = embed[(size_t)stok[m] * EE + kk + k];
            Bs[k][m] = W_ih[(n0 + m) * EE + kk + k];
        }
        __syncthreads();
        #pragma unroll
        for (int k = 0; k < 16; k++) {
            float4 a = *(const float4*)&As[k][ty * 4];
            float4 b = *(const float4*)&Bs[k][tx * 4];
            float av[4] = {a.x, a.y, a.z, a.w};
            float bv[4] = {b.x, b.y, b.z, b.w};
            #pragma unroll
            for (int i = 0; i < 4; i++)
                #pragma unroll
                for (int j = 0; j < 4; j++) acc[i][j] += av[i] * bv[j];
        }
        __syncthreads();
    }

    #pragma unroll
    for (int i = 0; i < 4; i++) {
        int m = m0 + ty * 4 + i;
        #pragma unroll
        for (int j = 0; j < 4; j++) {
            int n = n0 + tx * 4 + j;
            g_xproj[m * HH + n] = acc[i][j] + b_ih[n];
        }
    }
}

// ---------------------------------------------------------------------------
// Kernel 2: persistent recurrence. 128 CTAs x 256 thr, all co-resident.
// CTA owns 8 rows of W_hh in registers. Warp = (row-group of 4, batch-pair).
// Grid barrier per step via release/acquire atomics on g_ctr[t].
// ---------------------------------------------------------------------------
__global__ __launch_bounds__(256, 1) void rnn_kernel(
    const float* __restrict__ W_hh, const float* __restrict__ b_hh)
{
    __shared__ float h_sh[BB * HH];   // 32KB: previous step's h, all batches
    int tid = threadIdx.x;
    int lane = tid & 31, wid = tid >> 5;
    int jg = wid >> 2, bq = wid & 3;      // row-group (0..1), batch-quarter (0..3)
    int jbase = blockIdx.x * 8 + jg * 4;  // 4 rows per warp
    int b0 = bq * 2;                      // 2 batches per warp

    // W_hh rows for this warp's row-group, k-sliced by lane (k = lane + 32m)
    float w[4][32];
    #pragma unroll
    for (int jj = 0; jj < 4; jj++)
        #pragma unroll
        for (int m = 0; m < 32; m++)
            w[jj][m] = W_hh[(jbase + jj) * HH + lane + 32 * m];
    float bias[4];
    #pragma unroll
    for (int jj = 0; jj < 4; jj++) bias[jj] = b_hh[jbase + jj];

    #pragma unroll 1
    for (int t = 0; t < TT; t++) {
        float acc[4][2] = {};
        if (t > 0) {
            // stage hs[t-1] (32KB) into shared, L1-bypassing loads
            const float4* src = (const float4*)(g_hs + (t - 1) * (BB * HH));
            float4* dst = (float4*)h_sh;
            #pragma unroll
            for (int i = 0; i < 8; i++)
                dst[tid + 256 * i] = __ldcg(src + tid + 256 * i);
            __syncthreads();

            #pragma unroll
            for (int m = 0; m < 32; m++) {
                int k = lane + 32 * m;
                float h0 = h_sh[b0 * HH + k];
                float h1 = h_sh[b0 * HH + HH + k];
                #pragma unroll
                for (int jj = 0; jj < 4; jj++) {
                    acc[jj][0] += w[jj][m] * h0;
                    acc[jj][1] += w[jj][m] * h1;
                }
            }
            // full-warp reduction over k
            #pragma unroll
            for (int jj = 0; jj < 4; jj++)
                #pragma unroll
                for (int bb = 0; bb < 2; bb++)
                    #pragma unroll
                    for (int off = 16; off > 0; off >>= 1)
                        acc[jj][bb] += __shfl_xor_sync(0xffffffffu, acc[jj][bb], off);
        }

        if (lane < 8) {
            float mysum = 0.f, myb = 0.f;
            #pragma unroll
            for (int jj = 0; jj < 4; jj++)
                #pragma unroll
                for (int bb = 0; bb < 2; bb++)
                    if (lane == jj * 2 + bb) { mysum = acc[jj][bb]; myb = bias[jj]; }
            int j = jbase + (lane >> 1);
            int b = b0 + (lane & 1);
            float xp = g_xproj[(t * BB + b) * HH + j];
            float hv = tanhf(xp + myb + mysum);
            g_hs[t * (BB * HH) + b * HH + j] = hv;
        }

        // grid-wide barrier for step t
        __threadfence();
        __syncthreads();
        if (tid == 0) {
            asm volatile("red.release.gpu.global.add.u32 [%0], %1;"
                         :: "l"(&g_ctr[t]), "r"(1u) : "memory");
            unsigned v;
            do {
                asm volatile("ld.acquire.gpu.global.u32 %0, [%1];"
                             : "=r"(v) : "l"(&g_ctr[t]) : "memory");
            } while (v < GRID_RNN);
        }
        __syncthreads();
    }
}

// ---------------------------------------------------------------------------
// Kernel 3: FC. out[b][t][o] = sum_h hs[t*8+b][h]*W_fc[o][h] + b_fc[o]
// GEMM M=2048, N=32000, K=1024. 128x128 tiles, 256 thr, 8x8 micro, KC=8.
// ---------------------------------------------------------------------------
__global__ __launch_bounds__(256, 2) void fc_kernel(
    const float* __restrict__ W_fc, const float* __restrict__ b_fc,
    float* __restrict__ out)
{
    __shared__ float As[8][132];   // stride 132 (528B = 16*33, 16B aligned)
    __shared__ float Bs[8][132];
    int tid = threadIdx.x;
    int n0 = blockIdx.x * 128, m0 = blockIdx.y * 128;
    int tx = tid & 15, ty = tid >> 4;
    float acc[8][8] = {};

    int lm = tid >> 1;           // 0..127 (row within tile)
    int lk = (tid & 1) * 4;      // 0 or 4
    const float* Aptr = g_hs + (m0 + lm) * HH + lk;
    const float* Bptr = W_fc + (size_t)(n0 + lm) * HH + lk;

    #pragma unroll 1
    for (int kk = 0; kk < HH; kk += 8) {
        float4 a = *(const float4*)(Aptr + kk);
        float4 b = *(const float4*)(Bptr + kk);
        As[lk + 0][lm] = a.x; As[lk + 1][lm] = a.y;
        As[lk + 2][lm] = a.z; As[lk + 3][lm] = a.w;
        Bs[lk + 0][lm] = b.x; Bs[lk + 1][lm] = b.y;
        Bs[lk + 2][lm] = b.z; Bs[lk + 3][lm] = b.w;
        __syncthreads();
        #pragma unroll
        for (int k = 0; k < 8; k++) {
            float av[8], bv[8];
            *(float4*)&av[0] = *(const float4*)&As[k][ty * 8];
            *(float4*)&av[4] = *(const float4*)&As[k][ty * 8 + 4];
            *(float4*)&bv[0] = *(const float4*)&Bs[k][tx * 8];
            *(float4*)&bv[4] = *(const float4*)&Bs[k][tx * 8 + 4];
            #pragma unroll
            for (int i = 0; i < 8; i++)
                #pragma unroll
                for (int j = 0; j < 8; j++) acc[i][j] += av[i] * bv[j];
        }
        __syncthreads();
    }

    float bfc[8];
    #pragma unroll
    for (int j = 0; j < 8; j++) bfc[j] = b_fc[n0 + tx * 8 + j];

    #pragma unroll
    for (int i = 0; i < 8; i++) {
        int r = m0 + ty * 8 + i;
        int tt = r >> 3, bb = r & 7;
        float* orow = out + (size_t)(bb * TT + tt) * OO + n0 + tx * 8;
        float4 v0 = make_float4(acc[i][0] + bfc[0], acc[i][1] + bfc[1],
                                acc[i][2] + bfc[2], acc[i][3] + bfc[3]);
        float4 v1 = make_float4(acc[i][4] + bfc[4], acc[i][5] + bfc[5],
                                acc[i][6] + bfc[6], acc[i][7] + bfc[7]);
        *(float4*)orow = v0;
        *(float4*)(orow + 4) = v1;
    }
}

// ---------------------------------------------------------------------------
extern "C" void kernel_launch(void* const* d_in, const int* in_sizes, int n_in,
                              void* d_out, int out_size)
{
    const void*  tokens = d_in[0];                 // int64 or int32, auto-detected
    const float* embed  = (const float*)d_in[1];   // [32000,512]
    const float* W_ih   = (const float*)d_in[2];   // [1024,512]
    const float* W_hh   = (const float*)d_in[3];   // [1024,1024]
    const float* b_ih   = (const float*)d_in[4];   // [1024]
    const float* b_hh   = (const float*)d_in[5];   // [1024]
    const float* W_fc   = (const float*)d_in[6];   // [32000,1024]
    const float* b_fc   = (const float*)d_in[7];   // [32000]
    float* out = (float*)d_out;                    // [8,256,32000]

    dim3 g1(HH / 64, MM / 64);       // 16 x 32
    xproj_kernel<<<g1, 256>>>(tokens, embed, W_ih, b_ih);

    rnn_kernel<<<GRID_RNN, 256>>>(W_hh, b_hh);

    dim3 g3(OO / 128, MM / 128);     // 250 x 16
    fc_kernel<<<g3, 256>>>(W_fc, b_fc, out);
}

// round 4
// speedup vs baseline: 3.4041x; 3.4041x over previous
#include <cuda_runtime.h>
#include <cuda_bf16.h>
#include <cstdint>

#define TT 256
#define BB 8
#define EE 512
#define HH 1024
#define OO 32000
#define MM (TT*BB)       // 2048
#define GRID_RNN 128
#define KK3 3072         // split-K': [hi|hi|lo] x [hi|lo|hi]

__device__ float g_xproj[MM*HH];
__device__ float g_hs[MM*HH];
__device__ unsigned g_ctr[TT];
__device__ __align__(16) __nv_bfloat16 g_Ab[(size_t)MM*KK3];   // 12.6 MB
__device__ __align__(16) __nv_bfloat16 g_Bb[(size_t)OO*KK3];   // 196.6 MB

// ===========================================================================
// Kernel 1: xproj (unchanged) + zero grid-barrier counters
// ===========================================================================
__global__ __launch_bounds__(256, 2) void xproj_kernel(
    const void* __restrict__ tokens_raw, const float* __restrict__ embed,
    const float* __restrict__ W_ih, const float* __restrict__ b_ih)
{
    if (blockIdx.x == 0 && blockIdx.y == 0 && threadIdx.x < TT)
        g_ctr[threadIdx.x] = 0;

    __shared__ float As[16][68];
    __shared__ float Bs[16][68];
    __shared__ int   stok[64];
    __shared__ int   mode64;

    int tid = threadIdx.x;
    int n0 = blockIdx.x * 64, m0 = blockIdx.y * 64;

    if (tid == 0) {
        const int* w = (const int*)tokens_raw;
        int z = 1;
        #pragma unroll 1
        for (int i = 1; i < 64; i += 2) if (w[i] != 0) z = 0;
        mode64 = z;
    }
    __syncthreads();
    if (tid < 64) {
        int r = m0 + tid; int tt = r >> 3, bb = r & 7;
        int idx = bb * TT + tt;
        stok[tid] = mode64 ? (int)((const long long*)tokens_raw)[idx]
                           : ((const int*)tokens_raw)[idx];
    }
    __syncthreads();

    int tx = tid & 15, ty = tid >> 4;
    float acc[4][4] = {};

    for (int kk = 0; kk < EE; kk += 16) {
        #pragma unroll
        for (int i = 0; i < 4; i++) {
            int lin = i * 256 + tid;
            int m = lin >> 4, k = lin & 15;
            As[k][m] = embed[(size_t)stok[m] * EE + kk + k];
            Bs[k][m] = W_ih[(n0 + m) * EE + kk + k];
        }
        __syncthreads();
        #pragma unroll
        for (int k = 0; k < 16; k++) {
            float4 a = *(const float4*)&As[k][ty * 4];
            float4 b = *(const float4*)&Bs[k][tx * 4];
            float av[4] = {a.x, a.y, a.z, a.w};
            float bv[4] = {b.x, b.y, b.z, b.w};
            #pragma unroll
            for (int i = 0; i < 4; i++)
                #pragma unroll
                for (int j = 0; j < 4; j++) acc[i][j] += av[i] * bv[j];
        }
        __syncthreads();
    }

    #pragma unroll
    for (int i = 0; i < 4; i++) {
        int m = m0 + ty * 4 + i;
        #pragma unroll
        for (int j = 0; j < 4; j++) {
            int n = n0 + tx * 4 + j;
            g_xproj[m * HH + n] = acc[i][j] + b_ih[n];
        }
    }
}

// ===========================================================================
// Kernel 2: persistent recurrence (unchanged)
// ===========================================================================
__global__ __launch_bounds__(256, 1) void rnn_kernel(
    const float* __restrict__ W_hh, const float* __restrict__ b_hh)
{
    __shared__ float h_sh[BB * HH];
    int tid = threadIdx.x;
    int lane = tid & 31, wid = tid >> 5;
    int jg = wid >> 2, bq = wid & 3;
    int jbase = blockIdx.x * 8 + jg * 4;
    int b0 = bq * 2;

    float w[4][32];
    #pragma unroll
    for (int jj = 0; jj < 4; jj++)
        #pragma unroll
        for (int m = 0; m < 32; m++)
            w[jj][m] = W_hh[(jbase + jj) * HH + lane + 32 * m];
    float bias[4];
    #pragma unroll
    for (int jj = 0; jj < 4; jj++) bias[jj] = b_hh[jbase + jj];

    #pragma unroll 1
    for (int t = 0; t < TT; t++) {
        float acc[4][2] = {};
        if (t > 0) {
            const float4* src = (const float4*)(g_hs + (t - 1) * (BB * HH));
            float4* dst = (float4*)h_sh;
            #pragma unroll
            for (int i = 0; i < 8; i++)
                dst[tid + 256 * i] = __ldcg(src + tid + 256 * i);
            __syncthreads();

            #pragma unroll
            for (int m = 0; m < 32; m++) {
                int k = lane + 32 * m;
                float h0 = h_sh[b0 * HH + k];
                float h1 = h_sh[b0 * HH + HH + k];
                #pragma unroll
                for (int jj = 0; jj < 4; jj++) {
                    acc[jj][0] += w[jj][m] * h0;
                    acc[jj][1] += w[jj][m] * h1;
                }
            }
            #pragma unroll
            for (int jj = 0; jj < 4; jj++)
                #pragma unroll
                for (int bb = 0; bb < 2; bb++)
                    #pragma unroll
                    for (int off = 16; off > 0; off >>= 1)
                        acc[jj][bb] += __shfl_xor_sync(0xffffffffu, acc[jj][bb], off);
        }

        if (lane < 8) {
            float mysum = 0.f, myb = 0.f;
            #pragma unroll
            for (int jj = 0; jj < 4; jj++)
                #pragma unroll
                for (int bb = 0; bb < 2; bb++)
                    if (lane == jj * 2 + bb) { mysum = acc[jj][bb]; myb = bias[jj]; }
            int j = jbase + (lane >> 1);
            int b = b0 + (lane & 1);
            float xp = g_xproj[(t * BB + b) * HH + j];
            float hv = tanhf(xp + myb + mysum);
            g_hs[t * (BB * HH) + b * HH + j] = hv;
        }

        __threadfence();
        __syncthreads();
        if (tid == 0) {
            asm volatile("red.release.gpu.global.add.u32 [%0], %1;"
                         :: "l"(&g_ctr[t]), "r"(1u) : "memory");
            unsigned v;
            do {
                asm volatile("ld.acquire.gpu.global.u32 %0, [%1];"
                             : "=r"(v) : "l"(&g_ctr[t]) : "memory");
            } while (v < GRID_RNN);
        }
        __syncthreads();
    }
}

// ===========================================================================
// Split kernels: fp32 -> bf16 3-term split layouts
// ===========================================================================
__global__ void split_w_kernel(const float* __restrict__ W) {
    size_t idx = (size_t)blockIdx.x * 256 + threadIdx.x;
    float w = W[idx];
    __nv_bfloat16 hi = __float2bfloat16(w);
    __nv_bfloat16 lo = __float2bfloat16(w - __bfloat162float(hi));
    size_t o = idx >> 10, k = idx & 1023;
    size_t base = o * KK3;
    g_Bb[base + k]        = hi;
    g_Bb[base + 1024 + k] = lo;
    g_Bb[base + 2048 + k] = hi;
}

__global__ void split_a_kernel() {
    size_t idx = (size_t)blockIdx.x * 256 + threadIdx.x;
    float a = g_hs[idx];
    __nv_bfloat16 hi = __float2bfloat16(a);
    __nv_bfloat16 lo = __float2bfloat16(a - __bfloat162float(hi));
    size_t m = idx >> 10, k = idx & 1023;
    size_t base = m * KK3;
    g_Ab[base + k]        = hi;
    g_Ab[base + 1024 + k] = hi;
    g_Ab[base + 2048 + k] = lo;
}

// ===========================================================================
// Kernel 3: FC via warp-level mma.sync (HMMA tensor path, base compute_103).
// C[2048,32000] = A'[2048,3072] x B'[32000,3072]^T, bf16 in, fp32 acc.
// CTA tile 128x128xKC64, 8 warps (2M x 4N), warp tile 64x32, cp.async
// double-buffer, SW128-swizzled smem, ldmatrix.x4 -> mma.m16n8k16.
// ===========================================================================
#define FC_NCH   (KK3/64)     // 48 chunks
#define FC_ABUF  16384        // bytes per A buffer (128 rows x 128B)
#define FC_BBUF  16384
#define FC_SM_A0 0
#define FC_SM_B0 16384
#define FC_SM_A1 32768
#define FC_SM_B1 49152
#define FC_SM_BIAS 65536
#define FC_SMEM_TOTAL (65536 + 512)

__device__ __forceinline__ uint32_t swz(uint32_t byte) {
    return byte ^ ((byte >> 3) & 0x70);
}

__device__ __forceinline__ void ldsm_x4(uint32_t& r0, uint32_t& r1,
                                        uint32_t& r2, uint32_t& r3, uint32_t a) {
    asm volatile("ldmatrix.sync.aligned.m8n8.x4.shared.b16 {%0,%1,%2,%3}, [%4];"
                 : "=r"(r0), "=r"(r1), "=r"(r2), "=r"(r3) : "r"(a));
}
__device__ __forceinline__ void mma16816(float* d, const uint32_t* a,
                                         const uint32_t* b) {
    asm volatile("mma.sync.aligned.m16n8k16.row.col.f32.bf16.bf16.f32 "
                 "{%0,%1,%2,%3}, {%4,%5,%6,%7}, {%8,%9}, {%0,%1,%2,%3};"
                 : "+f"(d[0]), "+f"(d[1]), "+f"(d[2]), "+f"(d[3])
                 : "r"(a[0]), "r"(a[1]), "r"(a[2]), "r"(a[3]),
                   "r"(b[0]), "r"(b[1]));
}
__device__ __forceinline__ void cp_async16(uint32_t saddr, const void* gaddr) {
    asm volatile("cp.async.cg.shared.global [%0], [%1], 16;"
                 :: "r"(saddr), "l"(gaddr));
}

__global__ void __launch_bounds__(256, 2) fc_mma_kernel(
    const float* __restrict__ b_fc, float* __restrict__ out)
{
    extern __shared__ char smem[];
    uint32_t sb = (uint32_t)__cvta_generic_to_shared(smem);
    int tid = threadIdx.x, wid = tid >> 5, lane = tid & 31;
    int m_tile = blockIdx.x & 15, n_tile = blockIdx.x >> 4;
    int m0 = m_tile * 128, n0 = n_tile * 128;
    int wm = wid >> 2, wn = wid & 3;        // 2 x 4 warps

    if (tid < 128)
        ((float*)(smem + FC_SM_BIAS))[tid] = b_fc[n0 + tid];

    // per-thread load slots: u = tid + i*256 over 1024 16B units per tile
    int ldrow = tid >> 3, ldc16 = tid & 7;  // +32 rows per i

    // issue chunk c into buffer s
    auto issue = [&](int c, int s) {
        uint32_t abase = sb + (s ? FC_SM_A1 : FC_SM_A0);
        uint32_t bbase = sb + (s ? FC_SM_B1 : FC_SM_B0);
        #pragma unroll
        for (int i = 0; i < 4; i++) {
            int row = ldrow + i * 32;
            uint32_t t = swz(row * 128 + ldc16 * 16);
            cp_async16(abase + t,
                       g_Ab + (size_t)(m0 + row) * KK3 + c * 64 + ldc16 * 8);
            cp_async16(bbase + t,
                       g_Bb + (size_t)(n0 + row) * KK3 + c * 64 + ldc16 * 8);
        }
        asm volatile("cp.async.commit_group;" ::: "memory");
    };

    issue(0, 0);
    issue(1, 1);

    float acc[4][4][4] = {};   // [mfrag][nfrag][c0..c3]

    // ldmatrix per-lane row components (tile-relative)
    int a_row = wm * 64 + (lane & 15);          // + f*16
    int a_colb = (lane >> 4) * 16;              // + ks*32
    int b_row = wn * 32 + (lane & 7) + ((lane >> 4) & 1) * 8;   // + pair*16
    int b_colb = ((lane >> 3) & 1) * 16;        // + ks*32

    #pragma unroll 1
    for (int c = 0; c < FC_NCH; c++) {
        int s = c & 1;
        asm volatile("cp.async.wait_group 1;" ::: "memory");
        __syncthreads();

        uint32_t abase = sb + (s ? FC_SM_A1 : FC_SM_A0);
        uint32_t bbase = sb + (s ? FC_SM_B1 : FC_SM_B0);

        #pragma unroll
        for (int ks = 0; ks < 4; ks++) {
            uint32_t a[4][4], b[2][4];
            #pragma unroll
            for (int f = 0; f < 4; f++)
                ldsm_x4(a[f][0], a[f][1], a[f][2], a[f][3],
                        abase + swz((a_row + f * 16) * 128 + ks * 32 + a_colb));
            #pragma unroll
            for (int p = 0; p < 2; p++)
                ldsm_x4(b[p][0], b[p][1], b[p][2], b[p][3],
                        bbase + swz((b_row + p * 16) * 128 + ks * 32 + b_colb));
            // b[p] regs: {n8frag(2p) b0,b1, n8frag(2p+1) b0,b1}
            #pragma unroll
            for (int f = 0; f < 4; f++) {
                #pragma unroll
                for (int p = 0; p < 2; p++) {
                    mma16816(acc[f][2 * p],     a[f], &b[p][0]);
                    mma16816(acc[f][2 * p + 1], a[f], &b[p][2]);
                }
            }
        }
        __syncthreads();
        if (c + 2 < FC_NCH) issue(c + 2, s);
    }

    // Epilogue
    const float* bsh = (const float*)(smem + FC_SM_BIAS);
    int tq = lane >> 2, tr = lane & 3;
    #pragma unroll
    for (int f = 0; f < 4; f++) {
        #pragma unroll
        for (int h = 0; h < 2; h++) {
            int r = m0 + wm * 64 + f * 16 + tq + h * 8;
            int tt = r >> 3, bb = r & 7;
            float* orow = out + (size_t)(bb * TT + tt) * OO;
            #pragma unroll
            for (int g = 0; g < 4; g++) {
                int n = n0 + wn * 32 + g * 8 + 2 * tr;
                float2 v;
                v.x = acc[f][g][2 * h + 0] + bsh[n - n0];
                v.y = acc[f][g][2 * h + 1] + bsh[n - n0 + 1];
                *(float2*)(orow + n) = v;
            }
        }
    }
}

// ===========================================================================
extern "C" void kernel_launch(void* const* d_in, const int* in_sizes, int n_in,
                              void* d_out, int out_size)
{
    const void*  tokens = d_in[0];
    const float* embed  = (const float*)d_in[1];
    const float* W_ih   = (const float*)d_in[2];
    const float* W_hh   = (const float*)d_in[3];
    const float* b_ih   = (const float*)d_in[4];
    const float* b_hh   = (const float*)d_in[5];
    const float* W_fc   = (const float*)d_in[6];
    const float* b_fc   = (const float*)d_in[7];
    float* out = (float*)d_out;

    static int smem_set = 0;
    if (!smem_set) {
        cudaFuncSetAttribute(fc_mma_kernel,
                             cudaFuncAttributeMaxDynamicSharedMemorySize,
                             FC_SMEM_TOTAL);
        smem_set = 1;
    }

    split_w_kernel<<<(OO * HH) / 256, 256>>>(W_fc);

    dim3 g1(HH / 64, MM / 64);
    xproj_kernel<<<g1, 256>>>(tokens, embed, W_ih, b_ih);

    rnn_kernel<<<GRID_RNN, 256>>>(W_hh, b_hh);

    split_a_kernel<<<(MM * HH) / 256, 256>>>();

    // bid = n_tile*16 + m_tile: 16 M-tiles of one N-tile adjacent in a wave
    fc_mma_kernel<<<(OO / 128) * (MM / 128), 256, FC_SMEM_TOTAL>>>(b_fc, out);
}

// round 7
// speedup vs baseline: 3.7245x; 1.0941x over previous
#include <cuda_runtime.h>
#include <cuda_bf16.h>
#include <cstdint>

#define TT 256
#define BB 8
#define EE 512
#define HH 1024
#define OO 32000
#define MM (TT*BB)       // 2048
#define GRID_RNN 128
#define KK3 3072         // A' split-K: [hi|hi|lo]
#define KKB 2048         // B' split-K storage: [hi|lo]; term3 re-reads hi

__device__ float g_xproj[MM*HH];
__device__ float g_hs[MM*HH];
__device__ unsigned g_ctr[TT];
__device__ __align__(16) __nv_bfloat16 g_Ab[(size_t)MM*KK3];   // 12.6 MB
__device__ __align__(16) __nv_bfloat16 g_Bb[(size_t)OO*KKB];   // 131 MB

// ===========================================================================
// Kernel 1: xproj + zero grid-barrier counters. Register double-buffered.
// ===========================================================================
__global__ __launch_bounds__(256, 2) void xproj_kernel(
    const void* __restrict__ tokens_raw, const float* __restrict__ embed,
    const float* __restrict__ W_ih, const float* __restrict__ b_ih)
{
    if (blockIdx.x == 0 && blockIdx.y == 0 && threadIdx.x < TT)
        g_ctr[threadIdx.x] = 0;

    __shared__ float As[16][68];
    __shared__ float Bs[16][68];
    __shared__ int   stok[64];
    __shared__ int   mode64;

    int tid = threadIdx.x;
    int n0 = blockIdx.x * 64, m0 = blockIdx.y * 64;

    if (tid == 0) {
        const int* w = (const int*)tokens_raw;
        int z = 1;
        #pragma unroll 1
        for (int i = 1; i < 64; i += 2) if (w[i] != 0) z = 0;
        mode64 = z;
    }
    __syncthreads();
    if (tid < 64) {
        int r = m0 + tid; int tt = r >> 3, bb = r & 7;
        int idx = bb * TT + tt;
        stok[tid] = mode64 ? (int)((const long long*)tokens_raw)[idx]
                           : ((const int*)tokens_raw)[idx];
    }
    __syncthreads();

    int tx = tid & 15, ty = tid >> 4;
    float acc[4][4] = {};

    // per-thread (m,k) load slots
    int lm[4], lk[4];
    #pragma unroll
    for (int i = 0; i < 4; i++) {
        int lin = i * 256 + tid;
        lm[i] = lin >> 4; lk[i] = lin & 15;
    }

    float a_pf[4], b_pf[4];
    #pragma unroll
    for (int i = 0; i < 4; i++) {
        a_pf[i] = __ldg(embed + (size_t)stok[lm[i]] * EE + lk[i]);
        b_pf[i] = __ldg(W_ih + (n0 + lm[i]) * EE + lk[i]);
    }

    #pragma unroll 1
    for (int kk = 0; kk < EE; kk += 16) {
        #pragma unroll
        for (int i = 0; i < 4; i++) {
            As[lk[i]][lm[i]] = a_pf[i];
            Bs[lk[i]][lm[i]] = b_pf[i];
        }
        __syncthreads();
        if (kk + 16 < EE) {
            #pragma unroll
            for (int i = 0; i < 4; i++) {
                a_pf[i] = __ldg(embed + (size_t)stok[lm[i]] * EE + kk + 16 + lk[i]);
                b_pf[i] = __ldg(W_ih + (n0 + lm[i]) * EE + kk + 16 + lk[i]);
            }
        }
        #pragma unroll
        for (int k = 0; k < 16; k++) {
            float4 a = *(const float4*)&As[k][ty * 4];
            float4 b = *(const float4*)&Bs[k][tx * 4];
            float av[4] = {a.x, a.y, a.z, a.w};
            float bv[4] = {b.x, b.y, b.z, b.w};
            #pragma unroll
            for (int i = 0; i < 4; i++)
                #pragma unroll
                for (int j = 0; j < 4; j++) acc[i][j] += av[i] * bv[j];
        }
        __syncthreads();
    }

    #pragma unroll
    for (int i = 0; i < 4; i++) {
        int m = m0 + ty * 4 + i;
        #pragma unroll
        for (int j = 0; j < 4; j++) {
            int n = n0 + tx * 4 + j;
            g_xproj[m * HH + n] = acc[i][j] + b_ih[n];
        }
    }
}

// ===========================================================================
// Kernel 2: persistent recurrence. Fence removed (release covers), constants
// hoisted, xproj prefetched before the dot product.
// ===========================================================================
__global__ __launch_bounds__(256, 1) void rnn_kernel(
    const float* __restrict__ W_hh, const float* __restrict__ b_hh)
{
    __shared__ float h_sh[BB * HH];
    int tid = threadIdx.x;
    int lane = tid & 31, wid = tid >> 5;
    int jg = wid >> 2, bq = wid & 3;
    int jbase = blockIdx.x * 8 + jg * 4;
    int b0 = bq * 2;

    float w[4][32];
    #pragma unroll
    for (int jj = 0; jj < 4; jj++)
        #pragma unroll
        for (int m = 0; m < 32; m++)
            w[jj][m] = W_hh[(jbase + jj) * HH + lane + 32 * m];

    // per-thread output assignment (lane<8 writers), constant over t
    int sel_j = lane >> 1, sel_b = lane & 1;
    int out_j = jbase + sel_j;
    int out_b = b0 + sel_b;
    float myb = b_hh[out_j];

    #pragma unroll 1
    for (int t = 0; t < TT; t++) {
        float xp = 0.f;
        if (lane < 8) xp = g_xproj[(t * BB + out_b) * HH + out_j];

        float acc[4][2] = {};
        if (t > 0) {
            const float4* src = (const float4*)(g_hs + (t - 1) * (BB * HH));
            float4* dst = (float4*)h_sh;
            #pragma unroll
            for (int i = 0; i < 8; i++)
                dst[tid + 256 * i] = __ldcg(src + tid + 256 * i);
            __syncthreads();

            #pragma unroll
            for (int m = 0; m < 32; m++) {
                int k = lane + 32 * m;
                float h0 = h_sh[b0 * HH + k];
                float h1 = h_sh[b0 * HH + HH + k];
                #pragma unroll
                for (int jj = 0; jj < 4; jj++) {
                    acc[jj][0] += w[jj][m] * h0;
                    acc[jj][1] += w[jj][m] * h1;
                }
            }
            #pragma unroll
            for (int jj = 0; jj < 4; jj++)
                #pragma unroll
                for (int bb = 0; bb < 2; bb++)
                    #pragma unroll
                    for (int off = 16; off > 0; off >>= 1)
                        acc[jj][bb] += __shfl_xor_sync(0xffffffffu, acc[jj][bb], off);
        }

        if (lane < 8) {
            float mysum = 0.f;
            #pragma unroll
            for (int jj = 0; jj < 4; jj++)
                #pragma unroll
                for (int bb = 0; bb < 2; bb++)
                    if (sel_j == jj && sel_b == bb) mysum = acc[jj][bb];
            float hv = tanhf(xp + myb + mysum);
            g_hs[t * (BB * HH) + out_b * HH + out_j] = hv;
        }

        // grid barrier: syncthreads (CTA hb) -> release-add -> acquire-poll
        __syncthreads();
        if (tid == 0) {
            asm volatile("red.release.gpu.global.add.u32 [%0], %1;"
                         :: "l"(&g_ctr[t]), "r"(1u) : "memory");
            unsigned v;
            do {
                asm volatile("ld.acquire.gpu.global.u32 %0, [%1];"
                             : "=r"(v) : "l"(&g_ctr[t]) : "memory");
            } while (v < GRID_RNN);
        }
        __syncthreads();
    }
}

// ===========================================================================
// Split kernels. A' = [a_hi | a_hi | a_lo] (K=3072); B' = [b_hi | b_lo] (K=2048)
// term1: A blk0 x B hi; term2: A blk1 x B lo; term3: A blk2 x B hi (re-read).
// ===========================================================================
__global__ void split_w_kernel(const float* __restrict__ W) {
    size_t idx = (size_t)blockIdx.x * 256 + threadIdx.x;
    float w = W[idx];
    __nv_bfloat16 hi = __float2bfloat16(w);
    __nv_bfloat16 lo = __float2bfloat16(w - __bfloat162float(hi));
    size_t o = idx >> 10, k = idx & 1023;
    size_t base = o * KKB;
    g_Bb[base + k]        = hi;
    g_Bb[base + 1024 + k] = lo;
}

__global__ void split_a_kernel() {
    size_t idx = (size_t)blockIdx.x * 256 + threadIdx.x;
    float a = g_hs[idx];
    __nv_bfloat16 hi = __float2bfloat16(a);
    __nv_bfloat16 lo = __float2bfloat16(a - __bfloat162float(hi));
    size_t m = idx >> 10, k = idx & 1023;
    size_t base = m * KK3;
    g_Ab[base + k]        = hi;
    g_Ab[base + 1024 + k] = hi;
    g_Ab[base + 2048 + k] = lo;
}

// ===========================================================================
// Kernel 3: FC via mma.sync, 3-stage cp.async pipeline.
// CTA tile 128x128xKC64, 8 warps (2M x 4N), SW128 swizzle, ldmatrix.x4.
// ===========================================================================
#define FC_NCH   (KK3/64)     // 48 chunks
#define FC_STAGE 32768        // A(16K) + B(16K) per stage
#define FC_SM_BIAS (3*FC_STAGE)          // 98304
#define FC_SMEM_TOTAL (FC_SM_BIAS + 512)

__device__ __forceinline__ uint32_t swz(uint32_t byte) {
    return byte ^ ((byte >> 3) & 0x70);
}
__device__ __forceinline__ void ldsm_x4(uint32_t& r0, uint32_t& r1,
                                        uint32_t& r2, uint32_t& r3, uint32_t a) {
    asm volatile("ldmatrix.sync.aligned.m8n8.x4.shared.b16 {%0,%1,%2,%3}, [%4];"
                 : "=r"(r0), "=r"(r1), "=r"(r2), "=r"(r3) : "r"(a));
}
__device__ __forceinline__ void mma16816(float* d, const uint32_t* a,
                                         const uint32_t* b) {
    asm volatile("mma.sync.aligned.m16n8k16.row.col.f32.bf16.bf16.f32 "
                 "{%0,%1,%2,%3}, {%4,%5,%6,%7}, {%8,%9}, {%0,%1,%2,%3};"
                 : "+f"(d[0]), "+f"(d[1]), "+f"(d[2]), "+f"(d[3])
                 : "r"(a[0]), "r"(a[1]), "r"(a[2]), "r"(a[3]),
                   "r"(b[0]), "r"(b[1]));
}
__device__ __forceinline__ void cp_async16(uint32_t saddr, const void* gaddr) {
    asm volatile("cp.async.cg.shared.global [%0], [%1], 16;"
                 :: "r"(saddr), "l"(gaddr));
}

__global__ void __launch_bounds__(256, 2) fc_mma_kernel(
    const float* __restrict__ b_fc, float* __restrict__ out)
{
    extern __shared__ char smem[];
    uint32_t sb = (uint32_t)__cvta_generic_to_shared(smem);
    int tid = threadIdx.x, wid = tid >> 5, lane = tid & 31;
    int m_tile = blockIdx.x & 15, n_tile = blockIdx.x >> 4;
    int m0 = m_tile * 128, n0 = n_tile * 128;
    int wm = wid >> 2, wn = wid & 3;        // 2 x 4 warps

    if (tid < 128)
        ((float*)(smem + FC_SM_BIAS))[tid] = b_fc[n0 + tid];

    int ldrow = tid >> 3, ldc16 = tid & 7;

    // issue chunk c into stage buffer s (A at s*32K, B at s*32K+16K)
    auto issue = [&](int c, int s) {
        uint32_t abase = sb + s * FC_STAGE;
        uint32_t bbase = abase + 16384;
        int a_koff = c * 64;
        int b_koff = (c & 15) * 64 + (((c >> 4) == 1) ? 1024 : 0);
        #pragma unroll
        for (int i = 0; i < 4; i++) {
            int row = ldrow + i * 32;
            uint32_t t = swz(row * 128 + ldc16 * 16);
            cp_async16(abase + t,
                       g_Ab + (size_t)(m0 + row) * KK3 + a_koff + ldc16 * 8);
            cp_async16(bbase + t,
                       g_Bb + (size_t)(n0 + row) * KKB + b_koff + ldc16 * 8);
        }
        asm volatile("cp.async.commit_group;" ::: "memory");
    };

    issue(0, 0);
    issue(1, 1);
    issue(2, 2);

    float acc[4][4][4] = {};

    int a_row = wm * 64 + (lane & 15);
    int a_colb = (lane >> 4) * 16;
    int b_row = wn * 32 + (lane & 7) + ((lane >> 4) & 1) * 8;
    int b_colb = ((lane >> 3) & 1) * 16;

    #pragma unroll 1
    for (int c = 0; c < FC_NCH; c++) {
        int s = c % 3;
        asm volatile("cp.async.wait_group 2;" ::: "memory");
        __syncthreads();

        uint32_t abase = sb + s * FC_STAGE;
        uint32_t bbase = abase + 16384;

        #pragma unroll
        for (int ks = 0; ks < 4; ks++) {
            uint32_t a[4][4], b[2][4];
            #pragma unroll
            for (int f = 0; f < 4; f++)
                ldsm_x4(a[f][0], a[f][1], a[f][2], a[f][3],
                        abase + swz((a_row + f * 16) * 128 + ks * 32 + a_colb));
            #pragma unroll
            for (int p = 0; p < 2; p++)
                ldsm_x4(b[p][0], b[p][1], b[p][2], b[p][3],
                        bbase + swz((b_row + p * 16) * 128 + ks * 32 + b_colb));
            #pragma unroll
            for (int f = 0; f < 4; f++) {
                #pragma unroll
                for (int p = 0; p < 2; p++) {
                    mma16816(acc[f][2 * p],     a[f], &b[p][0]);
                    mma16816(acc[f][2 * p + 1], a[f], &b[p][2]);
                }
            }
        }
        __syncthreads();
        if (c + 3 < FC_NCH) issue(c + 3, s);
    }

    // Epilogue
    const float* bsh = (const float*)(smem + FC_SM_BIAS);
    int tq = lane >> 2, tr = lane & 3;
    #pragma unroll
    for (int f = 0; f < 4; f++) {
        #pragma unroll
        for (int h = 0; h < 2; h++) {
            int r = m0 + wm * 64 + f * 16 + tq + h * 8;
            int tt = r >> 3, bb = r & 7;
            float* orow = out + (size_t)(bb * TT + tt) * OO;
            #pragma unroll
            for (int g = 0; g < 4; g++) {
                int n = n0 + wn * 32 + g * 8 + 2 * tr;
                float2 v;
                v.x = acc[f][g][2 * h + 0] + bsh[n - n0];
                v.y = acc[f][g][2 * h + 1] + bsh[n - n0 + 1];
                *(float2*)(orow + n) = v;
            }
        }
    }
}

// ===========================================================================
extern "C" void kernel_launch(void* const* d_in, const int* in_sizes, int n_in,
                              void* d_out, int out_size)
{
    const void*  tokens = d_in[0];
    const float* embed  = (const float*)d_in[1];
    const float* W_ih   = (const float*)d_in[2];
    const float* W_hh   = (const float*)d_in[3];
    const float* b_ih   = (const float*)d_in[4];
    const float* b_hh   = (const float*)d_in[5];
    const float* W_fc   = (const float*)d_in[6];
    const float* b_fc   = (const float*)d_in[7];
    float* out = (float*)d_out;

    static int smem_set = 0;
    if (!smem_set) {
        cudaFuncSetAttribute(fc_mma_kernel,
                             cudaFuncAttributeMaxDynamicSharedMemorySize,
                             FC_SMEM_TOTAL);
        smem_set = 1;
    }

    split_w_kernel<<<(OO * HH) / 256, 256>>>(W_fc);

    dim3 g1(HH / 64, MM / 64);
    xproj_kernel<<<g1, 256>>>(tokens, embed, W_ih, b_ih);

    rnn_kernel<<<GRID_RNN, 256>>>(W_hh, b_hh);

    split_a_kernel<<<(MM * HH) / 256, 256>>>();

    fc_mma_kernel<<<(OO / 128) * (MM / 128), 256, FC_SMEM_TOTAL>>>(b_fc, out);
}